// round 9
// baseline (speedup 1.0000x reference)
#include <cuda_runtime.h>
#include <math.h>

#define N_FFT   2048
#define HOP     512
#define NT      2880000
#define NFRAMES 5626            // 1 + NT/HOP
#define NPAIRS  2813            // NFRAMES/2
#define PAD     1024            // N_FFT/2
#define NCH     2

#define CHUNK     512
#define WARM      16384
#define NC        5625          // NT / CHUNK (exact)
#define NTILES    528           // (WARM + CHUNK) / 32
#define WARMTILES 512           // WARM / 32

#define TWO_PI_F 6.2831853071795864769f
#define LN10_F   2.3025850929940457f

// Scratch (device globals — no allocation allowed)
__device__ float g_sigA[NCH * NT];
__device__ float g_sigB[NCH * NT];
__device__ float g_frames[NCH * NFRAMES * N_FFT];   // reused as gs after OLA4
__device__ float g_win[N_FFT];

struct C2 { float x, y; };
__device__ __forceinline__ C2 cmulC(C2 a, C2 b) { return { a.x*b.x - a.y*b.y, a.x*b.y + a.y*b.x }; }
__device__ __forceinline__ C2 caddC(C2 a, C2 b) { return { a.x + b.x, a.y + b.y }; }
__device__ __forceinline__ C2 csubC(C2 a, C2 b) { return { a.x - b.x, a.y - b.y }; }

__device__ __forceinline__ int SWZ(int p) { return p + (p >> 5); }

// fill hann window (accurate path, computed once per launch)
__global__ void win_init_kernel()
{
    int j = blockIdx.x * blockDim.x + threadIdx.x;
    if (j < N_FFT)
        g_win[j] = 0.5f - 0.5f * cosf((TWO_PI_F / (float)N_FFT) * (float)j);
}

template<int SGN>
__device__ __forceinline__ void dft8(C2 v[8]) {
    const float r = 0.70710678118654752f;
    const float S = (float)SGN;
    C2 a0 = caddC(v[0], v[4]), a1 = csubC(v[0], v[4]);
    C2 a2 = caddC(v[2], v[6]), a3 = csubC(v[2], v[6]);
    C2 E0 = caddC(a0, a2), E2 = csubC(a0, a2);
    C2 E1 = { a1.x - S * a3.y, a1.y + S * a3.x };
    C2 E3 = { a1.x + S * a3.y, a1.y - S * a3.x };
    C2 b0 = caddC(v[1], v[5]), b1 = csubC(v[1], v[5]);
    C2 b2 = caddC(v[3], v[7]), b3 = csubC(v[3], v[7]);
    C2 O0 = caddC(b0, b2), O2 = csubC(b0, b2);
    C2 O1 = { b1.x - S * b3.y, b1.y + S * b3.x };
    C2 O3 = { b1.x + S * b3.y, b1.y - S * b3.x };
    C2 T1 = { r * (O1.x - S * O1.y), r * (O1.y + S * O1.x) };
    C2 T2 = { -S * O2.y, S * O2.x };
    C2 T3 = { -r * (O3.x + S * O3.y), r * (S * O3.x - O3.y) };
    v[0] = caddC(E0, O0); v[4] = csubC(E0, O0);
    v[1] = caddC(E1, T1); v[5] = csubC(E1, T1);
    v[2] = caddC(E2, T2); v[6] = csubC(E2, T2);
    v[3] = caddC(E3, T3); v[7] = csubC(E3, T3);
}

// 16-point DFT: two dft8 halves + constant rotations
template<int SGN>
__device__ __forceinline__ void dft16(C2 v[16]) {
    const float S = (float)SGN;
    const float c1 = 0.92387953251128675613f;   // cos(pi/8)
    const float s1 = 0.38268343236508977173f;   // sin(pi/8)
    const float r  = 0.70710678118654752440f;
    C2 e[8], o[8];
#pragma unroll
    for (int i = 0; i < 8; ++i) { e[i] = v[2*i]; o[i] = v[2*i+1]; }
    dft8<SGN>(e);
    dft8<SGN>(o);
    o[1] = cmulC(o[1], C2{ c1, S*s1});
    o[2] = cmulC(o[2], C2{ r,  S*r });
    o[3] = cmulC(o[3], C2{ s1, S*c1});
    o[4] = C2{ -S*o[4].y, S*o[4].x };
    o[5] = cmulC(o[5], C2{-s1, S*c1});
    o[6] = cmulC(o[6], C2{-r,  S*r });
    o[7] = cmulC(o[7], C2{-c1, S*s1});
#pragma unroll
    for (int k = 0; k < 8; ++k) { v[k] = caddC(e[k], o[k]); v[k+8] = csubC(e[k], o[k]); }
}

// twiddle powers W[1..15] of w1 via a depth-4 product tree (was: depth-15 serial chain)
__device__ __forceinline__ void twiddle_pows(C2 w1, C2 W[16]) {
    W[1] = w1;
    W[2] = cmulC(w1, w1);
    W[4] = cmulC(W[2], W[2]);
    W[8] = cmulC(W[4], W[4]);
    W[3] = cmulC(W[2], w1);
    W[5] = cmulC(W[4], w1);
    W[6] = cmulC(W[4], W[2]);
    W[7] = cmulC(W[4], W[3]);
    W[9]  = cmulC(W[8], w1);
    W[10] = cmulC(W[8], W[2]);
    W[11] = cmulC(W[8], W[3]);
    W[12] = cmulC(W[8], W[4]);
    W[13] = cmulC(W[8], W[5]);
    W[14] = cmulC(W[8], W[6]);
    W[15] = cmulC(W[8], W[7]);
}

// one radix-16 exchange stage
template<int SGN>
__device__ __forceinline__ void stage16(float2* sh, int M, int j, int base) {
    const int span = M >> 4;
    const int p0 = base + j;
    C2 v[16];
#pragma unroll
    for (int k = 0; k < 16; ++k) {
        float2 t = sh[SWZ(p0 + k * span)];
        v[k] = { t.x, t.y };
    }
    float sn, cs;
    __sincosf(((float)SGN * TWO_PI_F) * ((float)j / (float)M), &sn, &cs);
    C2 W[16];
    twiddle_pows(C2{ cs, sn }, W);
    if (SGN < 0) {
        dft16<-1>(v);
#pragma unroll
        for (int k = 1; k < 16; ++k) v[k] = cmulC(v[k], W[k]);
    } else {
#pragma unroll
        for (int k = 1; k < 16; ++k) v[k] = cmulC(v[k], W[k]);
        dft16<1>(v);
    }
#pragma unroll
    for (int k = 0; k < 16; ++k)
        sh[SWZ(p0 + k * span)] = make_float2(v[k].x, v[k].y);
}

// One block = one (channel, frame-pair). Two real frames packed into one complex FFT.
// 2048 = 16 x 16 x 8: two radix-16 exchange stages + fused radix-8 with real/even mask.
// storage p = d1*128 + d2*8 + i  <->  frequency k = d1 + 16*d2 + 256*i
__global__ void __launch_bounds__(128)
eq_pair_kernel(const float* __restrict__ x, float* __restrict__ frames,
               const float* __restrict__ gain_db_ptr, float fc)
{
    __shared__ float2 sh[N_FFT + (N_FFT >> 5)];

    const int tid = threadIdx.x;
    const int P = blockIdx.x;
    const int c = blockIdx.y;
    const int f0 = 2 * P;

    const float* xc = x + c * NT;

#pragma unroll
    for (int k = 0; k < 16; ++k) {
        int j = tid + 128 * k;
        float w = g_win[j];
        int s0 = f0 * HOP + j - PAD;
        if (s0 < 0) s0 = -s0;
        if (s0 >= NT) s0 = 2 * NT - 2 - s0;
        int s1 = (f0 + 1) * HOP + j - PAD;
        if (s1 < 0) s1 = -s1;
        if (s1 >= NT) s1 = 2 * NT - 2 - s1;
        sh[SWZ(j)] = make_float2(xc[s0] * w, xc[s1] * w);
    }
    __syncthreads();

    stage16<-1>(sh, 2048, tid, 0);
    __syncthreads();
    stage16<-1>(sh, 128, tid & 7, (tid >> 3) << 7);
    __syncthreads();

    // fused: forward radix-8 + mask + inverse radix-8 (2 groups/thread)
    {
        float gdb = gain_db_ptr[0];
        float gm1 = __expf(gdb * 0.05f * LN10_F) - 1.f;
        float inv_fc = 1.f / fc;
#pragma unroll
        for (int h = 0; h < 2; ++h) {
            int base = tid * 16 + h * 8;
            C2 u[8];
#pragma unroll
            for (int i = 0; i < 8; ++i) {
                float2 t = sh[SWZ(base + i)];
                u[i] = { t.x, t.y };
            }
            dft8<-1>(u);
            int d1 = (base >> 7) & 15, d2 = (base >> 3) & 15;
            int kbase = d1 + (d2 << 4);
#pragma unroll
            for (int i = 0; i < 8; ++i) {
                int kk = kbase + (i << 8);
                int ks = min(kk, N_FFT - kk);
                float fr = (float)ks * (24000.f / 1024.f);
                float rr = (fr - fc) * inv_fc;    // q = 1
                float fac = 1.f + gm1 * __expf(-rr * rr);
                u[i].x *= fac; u[i].y *= fac;
            }
            dft8<1>(u);
#pragma unroll
            for (int i = 0; i < 8; ++i)
                sh[SWZ(base + i)] = make_float2(u[i].x, u[i].y);
        }
    }
    __syncthreads();

    stage16<1>(sh, 128, tid & 7, (tid >> 3) << 7);
    __syncthreads();
    stage16<1>(sh, 2048, tid, 0);
    __syncthreads();

    float* fo0 = frames + (c * NFRAMES + f0) * N_FFT;
    float* fo1 = fo0 + N_FFT;
#pragma unroll
    for (int k = 0; k < 16; ++k) {
        int j = tid + 128 * k;
        float2 t = sh[SWZ(j)];
        float s = g_win[j] * (1.f / (float)N_FFT);
        fo0[j] = t.x * s;
        fo1[j] = t.y * s;
    }
}

// OLA. Interior (all 4 frames present): wsum == 1.5 exactly (Hann^2, 4x overlap).
__device__ __forceinline__ float ola_at(const float* __restrict__ frames, int c, int t)
{
    int tt = t + PAD;
    int fhi = tt >> 9;
    if (tt >= (N_FFT - HOP) && fhi <= NFRAMES - 1) {
        const float* base = frames + c * NFRAMES * N_FFT;
        int f = fhi - 3;
        int n = tt - f * HOP;   // in [1536, 2048)
        float s = base[f * N_FFT + n]
                + base[(f + 1) * N_FFT + (n - HOP)]
                + base[(f + 2) * N_FFT + (n - 2 * HOP)]
                + base[(f + 3) * N_FFT + (n - 3 * HOP)];
        return s * (2.f / 3.f);
    }
    int fmax = fhi;                                    if (fmax > NFRAMES - 1) fmax = NFRAMES - 1;
    int fmin = (tt - (N_FFT - 1) + (HOP - 1)) / HOP;   if (fmin < 0) fmin = 0;
    float sum = 0.f, ws = 0.f;
    for (int f = fmin; f <= fmax; ++f) {
        int n = tt - f * HOP;
        sum += frames[(c * NFRAMES + f) * N_FFT + n];
        float w = g_win[n];
        ws += w * w;
    }
    return sum / (ws > 1e-11f ? ws : 1.f);
}

__global__ void ola_kernel(const float* __restrict__ frames, float* __restrict__ out)
{
    int idx = blockIdx.x * blockDim.x + threadIdx.x;
    if (idx >= NCH * NT) return;
    int c = idx / NT;
    int t = idx - c * NT;
    out[idx] = ola_at(frames, c, t);
}

// final OLA fused with gain-reduction computation
__global__ void ola_gr_kernel(const float* __restrict__ frames, float* __restrict__ out,
                              float* __restrict__ gr,
                              const float* __restrict__ thr_p, const float* __restrict__ ratio_p)
{
    int idx = blockIdx.x * blockDim.x + threadIdx.x;
    if (idx >= NCH * NT) return;
    int c = idx / NT;
    int t = idx - c * NT;
    float v = ola_at(frames, c, t);
    out[idx] = v;
    float thr = thr_p[0];
    float ratio = ratio_p[0];
    float aa = fabsf(v) + 1e-8f;
    float adb = 20.f * __log10f(aa);
    gr[idx] = fmaxf(adb - thr, 0.f) * (1.f - 1.f / ratio);
}

// Warp-cooperative compressor scan (R8 structure, unchanged).
// NOTE: launched TWICE this round as a timing probe — it is idempotent
// (reads sigA, writes gs; disjoint buffers), so the total-time delta vs R8
// equals the scan's true duration in timed-loop conditions.
__global__ void __launch_bounds__(128)
scan_kernel(const float* __restrict__ gr, float* __restrict__ gs,
            const float* __restrict__ att_p, const float* __restrict__ rel_p)
{
    __shared__ float sbuf[4][2][32][33];

    const int w = threadIdx.x >> 5;
    const int lane = threadIdx.x & 31;
    const int warpGlobal = blockIdx.x * 4 + w;
    const int chunkBase = warpGlobal * 32;
    if (chunkBase >= NC) return;                 // warp-uniform
    const int c = blockIdx.y;
    const int myChunk = chunkBase + lane;

    const float a_att = 1.f - __expf(-1.f / (att_p[0] * 48000.f));
    const float a_rel = 1.f - __expf(-1.f / (rel_p[0] * 48000.f));
    const float m_att = 1.f - a_att, m_rel = 1.f - a_rel;

    const float* grc = gr + c * NT;
    float* gsc = gs + c * NT;

    const int base00 = chunkBase * CHUNK - WARM + lane;
    const bool needClamp = (warpGlobal == 0) || (chunkBase + 32 > NC);

    float state = 0.f;

#define STEP(gv) state = fmaxf(fmaf(m_att, state, a_att * (gv)), fmaf(m_rel, state, a_rel * (gv)))

#define LOADTILE(d, b) do {                                             \
        int _b0 = base00 + (d) * 32;                                    \
        if (needClamp) {                                                \
            _Pragma("unroll 8")                                         \
            for (int r = 0; r < 32; ++r) {                              \
                int _a = _b0 + r * CHUNK;                               \
                _a = max(0, min(_a, NT - 1));                           \
                sbuf[w][b][r][lane] = grc[_a];                          \
            }                                                           \
        } else {                                                        \
            _Pragma("unroll 8")                                         \
            for (int r = 0; r < 32; ++r)                                \
                sbuf[w][b][r][lane] = grc[_b0 + r * CHUNK];             \
        }                                                               \
    } while (0)

    LOADTILE(0, 0);
    __syncwarp();

    for (int d = 0; d < NTILES; ++d) {
        if (d + 1 < NTILES) LOADTILE(d + 1, (d + 1) & 1);
        const int b = d & 1;
        const int tfirst = myChunk * CHUNK - WARM + d * 32;

        if (d < WARMTILES) {
            if (tfirst >= 1) {
#pragma unroll
                for (int j = 0; j < 32; ++j) { float g = sbuf[w][b][lane][j]; STEP(g); }
            } else {
#pragma unroll
                for (int j = 0; j < 32; ++j) {
                    if (tfirst + j >= 1) { float g = sbuf[w][b][lane][j]; STEP(g); }
                }
            }
        } else {
            if (tfirst >= 1) {
#pragma unroll
                for (int j = 0; j < 32; ++j) {
                    float g = sbuf[w][b][lane][j]; STEP(g);
                    sbuf[w][b][lane][j] = state;
                }
            } else {
#pragma unroll
                for (int j = 0; j < 32; ++j) {
                    if (tfirst + j >= 1) { float g = sbuf[w][b][lane][j]; STEP(g); }
                    sbuf[w][b][lane][j] = state;
                }
            }
            __syncwarp();
            int toff = (d - WARMTILES) * 32 + lane;
#pragma unroll 8
            for (int r = 0; r < 32; ++r) {
                int ch = chunkBase + r;
                if (ch < NC) gsc[ch * CHUNK + toff] = sbuf[w][b][r][lane];
            }
        }
        __syncwarp();
    }
#undef STEP
#undef LOADTILE
}

// apply smoothed gain + makeup, then saturation
__global__ void final_kernel(const float* __restrict__ x, const float* __restrict__ gs,
                             float* __restrict__ out,
                             const float* __restrict__ makeup_p, const float* __restrict__ sat_p)
{
    int idx = blockIdx.x * blockDim.x + threadIdx.x;
    if (idx >= NCH * NT) return;
    float mk = makeup_p[0];
    float sat = sat_p[0];
    float xv = x[idx];
    float aa = fabsf(xv) + 1e-8f;
    float gl = __expf((mk - gs[idx]) * 0.05f * LN10_F);
    float sgn = (xv > 0.f) ? 1.f : ((xv < 0.f) ? -1.f : 0.f);
    float y = sgn * aa * gl;
    if (sat > 1.f) {
        float z = y * sat;
        float e = __expf(2.f * z);
        y = ((e - 1.f) / (e + 1.f)) / sat;
    }
    out[idx] = y;
}

extern "C" void kernel_launch(void* const* d_in, const int* in_sizes, int n_in,
                              void* d_out, int out_size)
{
    const float* audio      = (const float*)d_in[0];
    const float* eq_low     = (const float*)d_in[1];
    const float* eq_lowmid  = (const float*)d_in[2];
    const float* eq_highmid = (const float*)d_in[3];
    const float* eq_high    = (const float*)d_in[4];
    const float* thr        = (const float*)d_in[5];
    const float* ratio      = (const float*)d_in[6];
    const float* attack     = (const float*)d_in[7];
    const float* release    = (const float*)d_in[8];
    const float* makeup     = (const float*)d_in[9];
    const float* satur      = (const float*)d_in[10];
    float* out = (float*)d_out;

    float *sigA, *sigB, *frames;
    cudaGetSymbolAddress((void**)&sigA, g_sigA);
    cudaGetSymbolAddress((void**)&sigB, g_sigB);
    cudaGetSymbolAddress((void**)&frames, g_frames);
    float* gs = frames;   // frames buffer reused after final OLA

    dim3 gEq(NPAIRS, NCH);
    const int EW = 256;
    int ewBlocks = (NCH * NT + EW - 1) / EW;

    win_init_kernel<<<(N_FFT + 255) / 256, 256>>>();

    // EQ band chain (ping-pong)
    eq_pair_kernel<<<gEq, 128>>>(audio, frames, eq_low, 100.f);
    ola_kernel<<<ewBlocks, EW>>>(frames, sigA);
    eq_pair_kernel<<<gEq, 128>>>(sigA, frames, eq_lowmid, 500.f);
    ola_kernel<<<ewBlocks, EW>>>(frames, sigB);
    eq_pair_kernel<<<gEq, 128>>>(sigB, frames, eq_highmid, 3000.f);
    ola_kernel<<<ewBlocks, EW>>>(frames, sigA);
    eq_pair_kernel<<<gEq, 128>>>(sigA, frames, eq_high, 10000.f);
    // band 4 OLA fused with gain-reduction: audio -> sigB, gr -> sigA
    ola_gr_kernel<<<ewBlocks, EW>>>(frames, sigB, sigA, thr, ratio);

    // compressor envelope — launched TWICE (idempotent) as a timing probe:
    // total_R9 - total_R8 = scan duration (+ 4*delta_eq from the twiddle tree,
    // which the ncu eq line quantifies independently)
    int nWarpsPerCh = (NC + 31) / 32;
    dim3 gScan((nWarpsPerCh + 3) / 4, NCH);
    scan_kernel<<<gScan, 128>>>(sigA, gs, attack, release);
    scan_kernel<<<gScan, 128>>>(sigA, gs, attack, release);

    // gain + saturation
    final_kernel<<<ewBlocks, EW>>>(sigB, gs, out, makeup, satur);
}

// round 10
// speedup vs baseline: 2.1119x; 2.1119x over previous
#include <cuda_runtime.h>
#include <math.h>

#define N_FFT   2048
#define HOP     512
#define NT      2880000
#define NFRAMES 5626            // 1 + NT/HOP
#define NPAIRS  2813            // NFRAMES/2
#define PAD     1024            // N_FFT/2
#define NCH     2

#define CHUNK     512
#define WARM      16384
#define NC        5625          // NT / CHUNK (exact)
#define NTILES    528           // (WARM + CHUNK) / 32
#define WARMTILES 512           // WARM / 32

#define TWO_PI_F 6.2831853071795864769f
#define LN10_F   2.3025850929940457f

// Scratch (device globals — no allocation allowed)
__device__ float g_sigA[NCH * NT];
__device__ float g_sigB[NCH * NT];
__device__ float g_frames[NCH * NFRAMES * N_FFT];   // reused as gs after OLA4
__device__ float g_win[N_FFT];

struct C2 { float x, y; };
__device__ __forceinline__ C2 cmulC(C2 a, C2 b) { return { a.x*b.x - a.y*b.y, a.x*b.y + a.y*b.x }; }
__device__ __forceinline__ C2 caddC(C2 a, C2 b) { return { a.x + b.x, a.y + b.y }; }
__device__ __forceinline__ C2 csubC(C2 a, C2 b) { return { a.x - b.x, a.y - b.y }; }

__device__ __forceinline__ int SWZ(int p) { return p + (p >> 5); }

// fill hann window (accurate path, computed once per launch)
__global__ void win_init_kernel()
{
    int j = blockIdx.x * blockDim.x + threadIdx.x;
    if (j < N_FFT)
        g_win[j] = 0.5f - 0.5f * cosf((TWO_PI_F / (float)N_FFT) * (float)j);
}

template<int SGN>
__device__ __forceinline__ void dft8(C2 v[8]) {
    const float r = 0.70710678118654752f;
    const float S = (float)SGN;
    C2 a0 = caddC(v[0], v[4]), a1 = csubC(v[0], v[4]);
    C2 a2 = caddC(v[2], v[6]), a3 = csubC(v[2], v[6]);
    C2 E0 = caddC(a0, a2), E2 = csubC(a0, a2);
    C2 E1 = { a1.x - S * a3.y, a1.y + S * a3.x };
    C2 E3 = { a1.x + S * a3.y, a1.y - S * a3.x };
    C2 b0 = caddC(v[1], v[5]), b1 = csubC(v[1], v[5]);
    C2 b2 = caddC(v[3], v[7]), b3 = csubC(v[3], v[7]);
    C2 O0 = caddC(b0, b2), O2 = csubC(b0, b2);
    C2 O1 = { b1.x - S * b3.y, b1.y + S * b3.x };
    C2 O3 = { b1.x + S * b3.y, b1.y - S * b3.x };
    C2 T1 = { r * (O1.x - S * O1.y), r * (O1.y + S * O1.x) };
    C2 T2 = { -S * O2.y, S * O2.x };
    C2 T3 = { -r * (O3.x + S * O3.y), r * (S * O3.x - O3.y) };
    v[0] = caddC(E0, O0); v[4] = csubC(E0, O0);
    v[1] = caddC(E1, T1); v[5] = csubC(E1, T1);
    v[2] = caddC(E2, T2); v[6] = csubC(E2, T2);
    v[3] = caddC(E3, T3); v[7] = csubC(E3, T3);
}

// 16-point DFT: two dft8 halves + constant rotations
template<int SGN>
__device__ __forceinline__ void dft16(C2 v[16]) {
    const float S = (float)SGN;
    const float c1 = 0.92387953251128675613f;   // cos(pi/8)
    const float s1 = 0.38268343236508977173f;   // sin(pi/8)
    const float r  = 0.70710678118654752440f;
    C2 e[8], o[8];
#pragma unroll
    for (int i = 0; i < 8; ++i) { e[i] = v[2*i]; o[i] = v[2*i+1]; }
    dft8<SGN>(e);
    dft8<SGN>(o);
    o[1] = cmulC(o[1], C2{ c1, S*s1});
    o[2] = cmulC(o[2], C2{ r,  S*r });
    o[3] = cmulC(o[3], C2{ s1, S*c1});
    o[4] = C2{ -S*o[4].y, S*o[4].x };
    o[5] = cmulC(o[5], C2{-s1, S*c1});
    o[6] = cmulC(o[6], C2{-r,  S*r });
    o[7] = cmulC(o[7], C2{-c1, S*s1});
#pragma unroll
    for (int k = 0; k < 8; ++k) { v[k] = caddC(e[k], o[k]); v[k+8] = csubC(e[k], o[k]); }
}

// twiddle powers W[1..15] of w1 via a depth-4 product tree
__device__ __forceinline__ void twiddle_pows(C2 w1, C2 W[16]) {
    W[1] = w1;
    W[2] = cmulC(w1, w1);
    W[4] = cmulC(W[2], W[2]);
    W[8] = cmulC(W[4], W[4]);
    W[3] = cmulC(W[2], w1);
    W[5] = cmulC(W[4], w1);
    W[6] = cmulC(W[4], W[2]);
    W[7] = cmulC(W[4], W[3]);
    W[9]  = cmulC(W[8], w1);
    W[10] = cmulC(W[8], W[2]);
    W[11] = cmulC(W[8], W[3]);
    W[12] = cmulC(W[8], W[4]);
    W[13] = cmulC(W[8], W[5]);
    W[14] = cmulC(W[8], W[6]);
    W[15] = cmulC(W[8], W[7]);
}

// one radix-16 exchange stage
template<int SGN>
__device__ __forceinline__ void stage16(float2* sh, int M, int j, int base) {
    const int span = M >> 4;
    const int p0 = base + j;
    C2 v[16];
#pragma unroll
    for (int k = 0; k < 16; ++k) {
        float2 t = sh[SWZ(p0 + k * span)];
        v[k] = { t.x, t.y };
    }
    float sn, cs;
    __sincosf(((float)SGN * TWO_PI_F) * ((float)j / (float)M), &sn, &cs);
    C2 W[16];
    twiddle_pows(C2{ cs, sn }, W);
    if (SGN < 0) {
        dft16<-1>(v);
#pragma unroll
        for (int k = 1; k < 16; ++k) v[k] = cmulC(v[k], W[k]);
    } else {
#pragma unroll
        for (int k = 1; k < 16; ++k) v[k] = cmulC(v[k], W[k]);
        dft16<1>(v);
    }
#pragma unroll
    for (int k = 0; k < 16; ++k)
        sh[SWZ(p0 + k * span)] = make_float2(v[k].x, v[k].y);
}

// One block = one (channel, frame-pair). Two real frames packed into one complex FFT.
// 2048 = 16 x 16 x 8: two radix-16 exchange stages + fused radix-8 with real/even mask.
// storage p = d1*128 + d2*8 + i  <->  frequency k = d1 + 16*d2 + 256*i
__global__ void __launch_bounds__(128)
eq_pair_kernel(const float* __restrict__ x, float* __restrict__ frames,
               const float* __restrict__ gain_db_ptr, float fc)
{
    __shared__ float2 sh[N_FFT + (N_FFT >> 5)];

    const int tid = threadIdx.x;
    const int P = blockIdx.x;
    const int c = blockIdx.y;
    const int f0 = 2 * P;

    const float* xc = x + c * NT;

#pragma unroll
    for (int k = 0; k < 16; ++k) {
        int j = tid + 128 * k;
        float w = g_win[j];
        int s0 = f0 * HOP + j - PAD;
        if (s0 < 0) s0 = -s0;
        if (s0 >= NT) s0 = 2 * NT - 2 - s0;
        int s1 = (f0 + 1) * HOP + j - PAD;
        if (s1 < 0) s1 = -s1;
        if (s1 >= NT) s1 = 2 * NT - 2 - s1;
        sh[SWZ(j)] = make_float2(xc[s0] * w, xc[s1] * w);
    }
    __syncthreads();

    stage16<-1>(sh, 2048, tid, 0);
    __syncthreads();
    stage16<-1>(sh, 128, tid & 7, (tid >> 3) << 7);
    __syncthreads();

    // fused: forward radix-8 + mask + inverse radix-8 (2 groups/thread)
    {
        float gdb = gain_db_ptr[0];
        float gm1 = __expf(gdb * 0.05f * LN10_F) - 1.f;
        float inv_fc = 1.f / fc;
#pragma unroll
        for (int h = 0; h < 2; ++h) {
            int base = tid * 16 + h * 8;
            C2 u[8];
#pragma unroll
            for (int i = 0; i < 8; ++i) {
                float2 t = sh[SWZ(base + i)];
                u[i] = { t.x, t.y };
            }
            dft8<-1>(u);
            int d1 = (base >> 7) & 15, d2 = (base >> 3) & 15;
            int kbase = d1 + (d2 << 4);
#pragma unroll
            for (int i = 0; i < 8; ++i) {
                int kk = kbase + (i << 8);
                int ks = min(kk, N_FFT - kk);
                float fr = (float)ks * (24000.f / 1024.f);
                float rr = (fr - fc) * inv_fc;    // q = 1
                float fac = 1.f + gm1 * __expf(-rr * rr);
                u[i].x *= fac; u[i].y *= fac;
            }
            dft8<1>(u);
#pragma unroll
            for (int i = 0; i < 8; ++i)
                sh[SWZ(base + i)] = make_float2(u[i].x, u[i].y);
        }
    }
    __syncthreads();

    stage16<1>(sh, 128, tid & 7, (tid >> 3) << 7);
    __syncthreads();
    stage16<1>(sh, 2048, tid, 0);
    __syncthreads();

    float* fo0 = frames + (c * NFRAMES + f0) * N_FFT;
    float* fo1 = fo0 + N_FFT;
#pragma unroll
    for (int k = 0; k < 16; ++k) {
        int j = tid + 128 * k;
        float2 t = sh[SWZ(j)];
        float s = g_win[j] * (1.f / (float)N_FFT);
        fo0[j] = t.x * s;
        fo1[j] = t.y * s;
    }
}

// OLA. Interior (all 4 frames present): wsum == 1.5 exactly (Hann^2, 4x overlap).
__device__ __forceinline__ float ola_at(const float* __restrict__ frames, int c, int t)
{
    int tt = t + PAD;
    int fhi = tt >> 9;
    if (tt >= (N_FFT - HOP) && fhi <= NFRAMES - 1) {
        const float* base = frames + c * NFRAMES * N_FFT;
        int f = fhi - 3;
        int n = tt - f * HOP;   // in [1536, 2048)
        float s = base[f * N_FFT + n]
                + base[(f + 1) * N_FFT + (n - HOP)]
                + base[(f + 2) * N_FFT + (n - 2 * HOP)]
                + base[(f + 3) * N_FFT + (n - 3 * HOP)];
        return s * (2.f / 3.f);
    }
    int fmax = fhi;                                    if (fmax > NFRAMES - 1) fmax = NFRAMES - 1;
    int fmin = (tt - (N_FFT - 1) + (HOP - 1)) / HOP;   if (fmin < 0) fmin = 0;
    float sum = 0.f, ws = 0.f;
    for (int f = fmin; f <= fmax; ++f) {
        int n = tt - f * HOP;
        sum += frames[(c * NFRAMES + f) * N_FFT + n];
        float w = g_win[n];
        ws += w * w;
    }
    return sum / (ws > 1e-11f ? ws : 1.f);
}

__global__ void ola_kernel(const float* __restrict__ frames, float* __restrict__ out)
{
    int idx = blockIdx.x * blockDim.x + threadIdx.x;
    if (idx >= NCH * NT) return;
    int c = idx / NT;
    int t = idx - c * NT;
    out[idx] = ola_at(frames, c, t);
}

// final OLA fused with gain-reduction computation
__global__ void ola_gr_kernel(const float* __restrict__ frames, float* __restrict__ out,
                              float* __restrict__ gr,
                              const float* __restrict__ thr_p, const float* __restrict__ ratio_p)
{
    int idx = blockIdx.x * blockDim.x + threadIdx.x;
    if (idx >= NCH * NT) return;
    int c = idx / NT;
    int t = idx - c * NT;
    float v = ola_at(frames, c, t);
    out[idx] = v;
    float thr = thr_p[0];
    float ratio = ratio_p[0];
    float aa = fabsf(v) + 1e-8f;
    float adb = 20.f * __log10f(aa);
    gr[idx] = fmaxf(adb - thr, 0.f) * (1.f - 1.f / ratio);
}

// Warp-cooperative compressor scan, pipelined:
//   1) LDG next tile into registers nx[32]   (latency hidden under this tile's chain)
//   2) preload gv[32] from smem (batched LDS, MLP covers 29-cyc latency)
//   3) pure-FFMA/FMNMX recurrence chain
//   4) STS nx -> alternate smem buffer (data already arrived; no exposed stall)
// This removes the LDG->STS false serialization that made R8's scan 590us (49 cyc/step
// vs the 8-cyc chain floor).
// Recurrence (exact, branchless): state' = max(fma(1-a_att,s,a_att*g), fma(1-a_rel,s,a_rel*g))
__global__ void __launch_bounds__(128, 1)
scan_kernel(const float* __restrict__ gr, float* __restrict__ gs,
            const float* __restrict__ att_p, const float* __restrict__ rel_p)
{
    __shared__ float sbuf[4][2][32][33];

    const int w = threadIdx.x >> 5;
    const int lane = threadIdx.x & 31;
    const int warpGlobal = blockIdx.x * 4 + w;
    const int chunkBase = warpGlobal * 32;
    if (chunkBase >= NC) return;                 // warp-uniform
    const int c = blockIdx.y;
    const int myChunk = chunkBase + lane;

    const float a_att = 1.f - __expf(-1.f / (att_p[0] * 48000.f));
    const float a_rel = 1.f - __expf(-1.f / (rel_p[0] * 48000.f));
    const float m_att = 1.f - a_att, m_rel = 1.f - a_rel;

    const float* grc = gr + c * NT;
    float* gsc = gs + c * NT;

    const int base00 = chunkBase * CHUNK - WARM + lane;
    const bool needClamp = (warpGlobal == 0) || (chunkBase + 32 > NC);

    float state = 0.f;
    float nx[32];

#define STEP(gv) state = fmaxf(fmaf(m_att, state, a_att * (gv)), fmaf(m_rel, state, a_rel * (gv)))

#define LOADREGS(d) do {                                                \
        int _b0 = base00 + (d) * 32;                                    \
        if (needClamp) {                                                \
            _Pragma("unroll")                                           \
            for (int r = 0; r < 32; ++r) {                              \
                int _a = _b0 + r * CHUNK;                               \
                _a = max(0, min(_a, NT - 1));                           \
                nx[r] = grc[_a];                                        \
            }                                                           \
        } else {                                                        \
            _Pragma("unroll")                                           \
            for (int r = 0; r < 32; ++r)                                \
                nx[r] = grc[_b0 + r * CHUNK];                           \
        }                                                               \
    } while (0)

#define STOREREGS(b) do {                                               \
        _Pragma("unroll")                                               \
        for (int r = 0; r < 32; ++r)                                    \
            sbuf[w][b][r][lane] = nx[r];                                \
    } while (0)

    LOADREGS(0);
    STOREREGS(0);
    __syncwarp();

    for (int d = 0; d < NTILES; ++d) {
        const int b = d & 1;
        // issue next tile's global loads FIRST (latency overlaps the chain below)
        if (d + 1 < NTILES) LOADREGS(d + 1);

        // batch-preload this tile's row into registers (independent LDS)
        float gv[32];
#pragma unroll
        for (int j = 0; j < 32; ++j) gv[j] = sbuf[w][b][lane][j];

        const int tfirst = myChunk * CHUNK - WARM + d * 32;

        if (d < WARMTILES) {
            if (tfirst >= 1) {
#pragma unroll
                for (int j = 0; j < 32; ++j) STEP(gv[j]);
            } else {
#pragma unroll
                for (int j = 0; j < 32; ++j) {
                    if (tfirst + j >= 1) STEP(gv[j]);
                }
            }
        } else {
            // store tile: scan + write states into smem, then cooperative coalesced store
            if (tfirst >= 1) {
#pragma unroll
                for (int j = 0; j < 32; ++j) {
                    STEP(gv[j]);
                    sbuf[w][b][lane][j] = state;
                }
            } else {
#pragma unroll
                for (int j = 0; j < 32; ++j) {
                    if (tfirst + j >= 1) STEP(gv[j]);
                    sbuf[w][b][lane][j] = state;   // at t=0 state==0 -> gs[0]=0
                }
            }
            __syncwarp();
            int toff = (d - WARMTILES) * 32 + lane;
#pragma unroll 8
            for (int r = 0; r < 32; ++r) {
                int ch = chunkBase + r;
                if (ch < NC) gsc[ch * CHUNK + toff] = sbuf[w][b][r][lane];
            }
        }

        // now stage next tile's data (registers already filled; no exposed LDG stall)
        if (d + 1 < NTILES) STOREREGS((d + 1) & 1);
        __syncwarp();
    }
#undef STEP
#undef LOADREGS
#undef STOREREGS
}

// apply smoothed gain + makeup, then saturation
__global__ void final_kernel(const float* __restrict__ x, const float* __restrict__ gs,
                             float* __restrict__ out,
                             const float* __restrict__ makeup_p, const float* __restrict__ sat_p)
{
    int idx = blockIdx.x * blockDim.x + threadIdx.x;
    if (idx >= NCH * NT) return;
    float mk = makeup_p[0];
    float sat = sat_p[0];
    float xv = x[idx];
    float aa = fabsf(xv) + 1e-8f;
    float gl = __expf((mk - gs[idx]) * 0.05f * LN10_F);
    float sgn = (xv > 0.f) ? 1.f : ((xv < 0.f) ? -1.f : 0.f);
    float y = sgn * aa * gl;
    if (sat > 1.f) {
        float z = y * sat;
        float e = __expf(2.f * z);
        y = ((e - 1.f) / (e + 1.f)) / sat;
    }
    out[idx] = y;
}

extern "C" void kernel_launch(void* const* d_in, const int* in_sizes, int n_in,
                              void* d_out, int out_size)
{
    const float* audio      = (const float*)d_in[0];
    const float* eq_low     = (const float*)d_in[1];
    const float* eq_lowmid  = (const float*)d_in[2];
    const float* eq_highmid = (const float*)d_in[3];
    const float* eq_high    = (const float*)d_in[4];
    const float* thr        = (const float*)d_in[5];
    const float* ratio      = (const float*)d_in[6];
    const float* attack     = (const float*)d_in[7];
    const float* release    = (const float*)d_in[8];
    const float* makeup     = (const float*)d_in[9];
    const float* satur      = (const float*)d_in[10];
    float* out = (float*)d_out;

    float *sigA, *sigB, *frames;
    cudaGetSymbolAddress((void**)&sigA, g_sigA);
    cudaGetSymbolAddress((void**)&sigB, g_sigB);
    cudaGetSymbolAddress((void**)&frames, g_frames);
    float* gs = frames;   // frames buffer reused after final OLA

    dim3 gEq(NPAIRS, NCH);
    const int EW = 256;
    int ewBlocks = (NCH * NT + EW - 1) / EW;

    win_init_kernel<<<(N_FFT + 255) / 256, 256>>>();

    // EQ band chain (ping-pong)
    eq_pair_kernel<<<gEq, 128>>>(audio, frames, eq_low, 100.f);
    ola_kernel<<<ewBlocks, EW>>>(frames, sigA);
    eq_pair_kernel<<<gEq, 128>>>(sigA, frames, eq_lowmid, 500.f);
    ola_kernel<<<ewBlocks, EW>>>(frames, sigB);
    eq_pair_kernel<<<gEq, 128>>>(sigB, frames, eq_highmid, 3000.f);
    ola_kernel<<<ewBlocks, EW>>>(frames, sigA);
    eq_pair_kernel<<<gEq, 128>>>(sigA, frames, eq_high, 10000.f);
    // band 4 OLA fused with gain-reduction: audio -> sigB, gr -> sigA
    ola_gr_kernel<<<ewBlocks, EW>>>(frames, sigB, sigA, thr, ratio);

    // pipelined warp-cooperative compressor envelope (gs into frames buffer)
    int nWarpsPerCh = (NC + 31) / 32;                  // 176
    dim3 gScan((nWarpsPerCh + 3) / 4, NCH);            // 44 x 2 blocks, 4 warps each
    scan_kernel<<<gScan, 128>>>(sigA, gs, attack, release);

    // gain + saturation
    final_kernel<<<ewBlocks, EW>>>(sigB, gs, out, makeup, satur);
}